// round 2
// baseline (speedup 1.0000x reference)
#include <cuda_runtime.h>
#include <cstdint>
#include <cstddef>
#include <math.h>

#define NUSERS 16384
#define HDIM 512
#define LATENT 256
#define MAX_ITEMS 50176
#define MAX_N (1 << 19)

// ---------------- device scratch (no allocation allowed) ----------------
__device__ float g_WencT[(size_t)MAX_ITEMS * HDIM];   // transposed encoder weights [items][512]
__device__ float g_x[(size_t)NUSERS * HDIM];          // tanh(agg + b_enc)
__device__ float g_enc[(size_t)NUSERS * LATENT];      // encoded
__device__ float g_dec[(size_t)NUSERS * HDIM];        // decoded
__device__ int   g_counts[NUSERS];
__device__ int   g_offsets[NUSERS + 1];
__device__ int   g_cursor[NUSERS];
__device__ int   g_idx[MAX_N];
__device__ float g_partials[MAX_N / 8 + 64];

// ---------------- transpose W_enc [512][items] -> g_WencT [items][512] ----------------
__global__ void k_transpose(const float* __restrict__ W, int items) {
    __shared__ float tile[32][33];
    int i = blockIdx.x * 32 + threadIdx.x;   // item (fast dim of W)
    int h = blockIdx.y * 32 + threadIdx.y;   // hidden
    if (i < items)
        tile[threadIdx.y][threadIdx.x] = W[(size_t)h * items + i];
    __syncthreads();
    int io = blockIdx.x * 32 + threadIdx.y;
    int ho = blockIdx.y * 32 + threadIdx.x;
    if (io < items)
        g_WencT[(size_t)io * HDIM + ho] = tile[threadIdx.x][threadIdx.y];
}

// ---------------- bucketing: histogram / scan / scatter ----------------
__global__ void k_init_counts() {
    int i = blockIdx.x * blockDim.x + threadIdx.x;
    if (i < NUSERS) g_counts[i] = 0;
}

__global__ void k_hist(const int* __restrict__ user, int n) {
    for (int i = blockIdx.x * blockDim.x + threadIdx.x; i < n; i += gridDim.x * blockDim.x)
        atomicAdd(&g_counts[user[i]], 1);
}

// single block, 1024 threads, 16 counts each -> exclusive prefix sum of 16384
__global__ void k_scan(int n) {
    __shared__ int wsum[32];
    const int tid = threadIdx.x, lane = tid & 31, warp = tid >> 5;
    const int base = tid * 16;
    int local[16];
    int sum = 0;
#pragma unroll
    for (int i = 0; i < 16; i++) { local[i] = sum; sum += g_counts[base + i]; }
    int v = sum;
#pragma unroll
    for (int off = 1; off < 32; off <<= 1) {
        int t = __shfl_up_sync(0xffffffffu, v, off);
        if (lane >= off) v += t;
    }
    if (lane == 31) wsum[warp] = v;
    __syncthreads();
    if (warp == 0) {
        int w = wsum[lane];
#pragma unroll
        for (int off = 1; off < 32; off <<= 1) {
            int t = __shfl_up_sync(0xffffffffu, w, off);
            if (lane >= off) w += t;
        }
        wsum[lane] = w;
    }
    __syncthreads();
    int excl = (warp ? wsum[warp - 1] : 0) + v - sum;
#pragma unroll
    for (int i = 0; i < 16; i++) {
        int o = excl + local[i];
        g_offsets[base + i] = o;
        g_cursor[base + i]  = o;
    }
    if (tid == 0) g_offsets[NUSERS] = n;
}

__global__ void k_scatter(const int* __restrict__ user, int n) {
    for (int i = blockIdx.x * blockDim.x + threadIdx.x; i < n; i += gridDim.x * blockDim.x) {
        int u = user[i];
        int pos = atomicAdd(&g_cursor[u], 1);
        g_idx[pos] = i;
    }
}

// ---------------- per-user segment sum + tanh(agg + b_enc) ----------------
__global__ void __launch_bounds__(128) k_aggregate(const int* __restrict__ item,
                                                   const float* __restrict__ rating,
                                                   const float* __restrict__ b_enc) {
    const int u = blockIdx.x;
    const int tid = threadIdx.x;
    const int beg = g_offsets[u], end = g_offsets[u + 1];
    __shared__ int   s_idx[512];
    __shared__ int   s_it[512];
    __shared__ float s_r[512];
    float4 acc = make_float4(0.f, 0.f, 0.f, 0.f);
    const int h4 = tid * 4;
    for (int ch = beg; ch < end; ch += 512) {
        int c = min(512, end - ch);
        for (int i = tid; i < c; i += 128) s_idx[i] = g_idx[ch + i];
        __syncthreads();
        if (tid == 0) {
            // sort indices -> deterministic fp accumulation order
            for (int i = 1; i < c; i++) {
                int key = s_idx[i];
                int j = i - 1;
                while (j >= 0 && s_idx[j] > key) { s_idx[j + 1] = s_idx[j]; j--; }
                s_idx[j + 1] = key;
            }
        }
        __syncthreads();
        for (int i = tid; i < c; i += 128) {
            int nn = s_idx[i];
            s_it[i] = item[nn];
            s_r[i]  = rating[nn];
        }
        __syncthreads();
        for (int e = 0; e < c; e++) {
            const float4 w = *reinterpret_cast<const float4*>(&g_WencT[(size_t)s_it[e] * HDIM + h4]);
            float r = s_r[e];
            acc.x += r * w.x; acc.y += r * w.y; acc.z += r * w.z; acc.w += r * w.w;
        }
        __syncthreads();
    }
    float4 b = *reinterpret_cast<const float4*>(&b_enc[h4]);
    float4 o = make_float4(tanhf(acc.x + b.x), tanhf(acc.y + b.y),
                           tanhf(acc.z + b.z), tanhf(acc.w + b.w));
    *reinterpret_cast<float4*>(&g_x[(size_t)u * HDIM + h4]) = o;
}

// ---------------- fused tanh GEMM: C[m][n] = tanh(bias[n] + sum_k A[m][k]*B[n][k]) ----------------
// SRC==0: A=g_x (K=512), C=g_enc (N=256). SRC==1: A=g_enc (K=256), C=g_dec (N=512).
template <int NCOLS, int KDIM, int SRC>
__global__ void __launch_bounds__(256) k_gemm_tanh(const float* __restrict__ B,
                                                   const float* __restrict__ bias) {
    const float* A = (SRC == 0) ? g_x : g_enc;
    float* C       = (SRC == 0) ? g_enc : g_dec;
    __shared__ float As[16][68];
    __shared__ float Bs[16][68];
    const int lid = threadIdx.x;
    const int row0 = blockIdx.y * 64, col0 = blockIdx.x * 64;
    const int ml = lid >> 2, k4 = (lid & 3) * 4;
    const int ty = lid >> 4, tx = lid & 15;
    float acc[4][4] = {};
    for (int k0 = 0; k0 < KDIM; k0 += 16) {
        float4 a  = *reinterpret_cast<const float4*>(&A[(size_t)(row0 + ml) * KDIM + k0 + k4]);
        float4 bv = *reinterpret_cast<const float4*>(&B[(size_t)(col0 + ml) * KDIM + k0 + k4]);
        As[k4 + 0][ml] = a.x;  As[k4 + 1][ml] = a.y;  As[k4 + 2][ml] = a.z;  As[k4 + 3][ml] = a.w;
        Bs[k4 + 0][ml] = bv.x; Bs[k4 + 1][ml] = bv.y; Bs[k4 + 2][ml] = bv.z; Bs[k4 + 3][ml] = bv.w;
        __syncthreads();
#pragma unroll
        for (int k = 0; k < 16; k++) {
            float av[4], bw[4];
#pragma unroll
            for (int i = 0; i < 4; i++) av[i] = As[k][ty * 4 + i];
#pragma unroll
            for (int j = 0; j < 4; j++) bw[j] = Bs[k][tx * 4 + j];
#pragma unroll
            for (int i = 0; i < 4; i++)
#pragma unroll
                for (int j = 0; j < 4; j++) acc[i][j] += av[i] * bw[j];
        }
        __syncthreads();
    }
#pragma unroll
    for (int i = 0; i < 4; i++) {
        int m = row0 + ty * 4 + i;
#pragma unroll
        for (int j = 0; j < 4; j++) {
            int nn = col0 + tx * 4 + j;
            C[(size_t)m * NCOLS + nn] = tanhf(acc[i][j] + bias[nn]);
        }
    }
}

// ---------------- prediction + per-block squared-error partials ----------------
__global__ void __launch_bounds__(256) k_pred(const int* __restrict__ tu,
                                              const int* __restrict__ ti,
                                              const float* __restrict__ tr,
                                              const float* __restrict__ Wdec,
                                              const float* __restrict__ bdec,
                                              float* __restrict__ out, int nt) {
    __shared__ float sh[8];
    const int gw = (blockIdx.x * 256 + threadIdx.x) >> 5;
    const int lane = threadIdx.x & 31;
    float se = 0.f;
    if (gw < nt) {
        int u  = tu[gw];
        int it = ti[gw];
        const float4* g = reinterpret_cast<const float4*>(&g_dec[(size_t)u * HDIM]);
        const float4* w = reinterpret_cast<const float4*>(&Wdec[(size_t)it * HDIM]);
        float s = 0.f;
#pragma unroll
        for (int q = 0; q < 4; q++) {
            float4 a = g[lane + 32 * q];
            float4 b = w[lane + 32 * q];
            s += a.x * b.x + a.y * b.y + a.z * b.z + a.w * b.w;
        }
#pragma unroll
        for (int off = 16; off; off >>= 1) s += __shfl_down_sync(0xffffffffu, s, off);
        if (lane == 0) {
            float p = s + bdec[it];
            out[gw] = p;
            float d = p - tr[gw];
            se = d * d;
        }
    }
    if (lane == 0) sh[threadIdx.x >> 5] = se;
    __syncthreads();
    if (threadIdx.x == 0) {
        float t = 0.f;
#pragma unroll
        for (int i = 0; i < 8; i++) t += sh[i];
        g_partials[blockIdx.x] = t;
    }
}

__global__ void __launch_bounds__(1024) k_loss(float* __restrict__ loc, int nblocks, int nt) {
    __shared__ float sh[32];
    const int tid = threadIdx.x;
    float s = 0.f;
    for (int i = tid; i < nblocks; i += 1024) s += g_partials[i];
#pragma unroll
    for (int off = 16; off; off >>= 1) s += __shfl_down_sync(0xffffffffu, s, off);
    if ((tid & 31) == 0) sh[tid >> 5] = s;
    __syncthreads();
    if (tid < 32) {
        float v = sh[tid];
#pragma unroll
        for (int off = 16; off; off >>= 1) v += __shfl_down_sync(0xffffffffu, v, off);
        if (tid == 0) *loc = v / (float)nt;
    }
}

// ---------------- launch ----------------
extern "C" void kernel_launch(void* const* d_in, const int* in_sizes, int n_in,
                              void* d_out, int out_size) {
    const int*   user   = (const int*)d_in[0];
    const int*   item   = (const int*)d_in[1];
    const float* rating = (const float*)d_in[2];
    const int*   tuser  = (const int*)d_in[3];
    const int*   titem  = (const int*)d_in[4];
    const float* trat   = (const float*)d_in[5];
    const float* W_enc  = (const float*)d_in[6];
    const float* b_enc  = (const float*)d_in[7];
    const float* W1     = (const float*)d_in[8];
    const float* b1     = (const float*)d_in[9];
    const float* W2     = (const float*)d_in[10];
    const float* b2     = (const float*)d_in[11];
    const float* W_dec  = (const float*)d_in[12];
    const float* b_dec  = (const float*)d_in[13];

    const int N     = in_sizes[0];
    const int NT    = in_sizes[3];
    const int items = in_sizes[13];   // b_dec has NUM_ITEMS elements

    float* pred = (float*)d_out;

    // 1. transpose encoder weights for contiguous row gathers
    k_transpose<<<dim3((items + 31) / 32, HDIM / 32), dim3(32, 32)>>>(W_enc, items);

    // 2. bucket interactions by user
    k_init_counts<<<64, 256>>>();
    k_hist<<<256, 256>>>(user, N);
    k_scan<<<1, 1024>>>(N);
    k_scatter<<<256, 256>>>(user, N);

    // 3. per-user segment sum + tanh(+b_enc)
    k_aggregate<<<NUSERS, 128>>>(item, rating, b_enc);

    // 4. encoder / decoder tanh GEMMs
    k_gemm_tanh<LATENT, HDIM, 0><<<dim3(LATENT / 64, NUSERS / 64), 256>>>(W1, b1);
    k_gemm_tanh<HDIM, LATENT, 1><<<dim3(HDIM / 64, NUSERS / 64), 256>>>(W2, b2);

    // 5. predictions + loss partials
    const int npb = (NT + 7) / 8;   // 8 warps/block, one target per warp
    k_pred<<<npb, 256>>>(tuser, titem, trat, W_dec, b_dec, pred, NT);

    // 6. final loss
    if (out_size > NT)
        k_loss<<<1, 1024>>>(pred + NT, npb, NT);
}